// round 4
// baseline (speedup 1.0000x reference)
#include <cuda_runtime.h>
#include <cuda_bf16.h>
#include <math.h>

#define NN 100000
#define NE 20000
#define NP 3200000
#define D  512
#define NREP  8                   // edge accumulator replicas (contention 160 -> 20)
#define NSREP 4                   // node accumulator replicas (contention 32 -> 8)

// ---------------- scratch (device globals; no allocation) ----------------
__device__ float4 g_m[NN];            // gelu(x @ Wmsg^T)         [N,4]
__device__ float4 g_u[NN];            // x @ Wupd^T + b           [N,4]
__device__ float4 g_ef[NE];           // edge means

// zero-initialized accumulators, packed so ONE memset clears them all
struct Scratch {
    float4 esum[NREP * NE];           // 2.56 MB
    float  ecnt[NREP * NE];           // 0.64 MB
    float4 nsum[NSREP * NN];          // 6.4 MB
    float  ncnt[NSREP * NN];          // 1.6 MB
};
__device__ Scratch g_s;

__device__ __forceinline__ float gelu_exact(float v) {
    return 0.5f * v * (1.0f + erff(v * 0.70710678118654752f));
}

// ---------------- packed f32x2 helpers (sm_100a) ----------------
__device__ __forceinline__ unsigned long long pk2(float a, float b) {
    unsigned long long r;
    asm("mov.b64 %0, {%1, %2};" : "=l"(r) : "f"(a), "f"(b));
    return r;
}
__device__ __forceinline__ void fma2(unsigned long long& d,
                                     unsigned long long a,
                                     unsigned long long b) {
    asm("fma.rn.f32x2 %0, %1, %2, %0;" : "+l"(d) : "l"(a), "l"(b));
}
__device__ __forceinline__ float upk_sum(unsigned long long v) {
    float x, y;
    asm("mov.b64 {%0, %1}, %2;" : "=f"(x), "=f"(y) : "l"(v));
    return x + y;
}

// ---------------- kernel 1: fused dual GEMV + GELU (f32x2) ----------------
// Each warp computes 2 rows; 8 output features (Wmsg rows 0-3, Wupd rows 4-7).
// W lives in shared (16KB). x read once, coalesced float4.
__global__ __launch_bounds__(256) void k_linear(
    const float4* __restrict__ x4,      // [N, 128] float4
    const float4* __restrict__ wmsg4,   // [4, 128]
    const float4* __restrict__ wupd4,   // [4, 128]
    const float*  __restrict__ b_upd)   // [4]
{
    __shared__ float4 sW[8 * 128];
    __shared__ float  sB[4];

    int t = threadIdx.x;
    for (int i = t; i < 4 * 128; i += 256) sW[i] = wmsg4[i];
    for (int i = t; i < 4 * 128; i += 256) sW[4 * 128 + i] = wupd4[i];
    if (t < 4) sB[t] = b_upd[t];
    __syncthreads();

    int warp = t >> 5;
    int lane = t & 31;
    int row0 = (blockIdx.x * 8 + warp) * 2;   // N = 100000 = 6250 blocks * 16 rows

    unsigned long long acc2[2][8];
    #pragma unroll
    for (int r = 0; r < 2; r++)
        #pragma unroll
        for (int k = 0; k < 8; k++) acc2[r][k] = 0ull;

    #pragma unroll
    for (int i = 0; i < 4; i++) {
        int c = i * 32 + lane;                // float4 column index 0..127
        unsigned long long wlo[8], whi[8];
        #pragma unroll
        for (int k = 0; k < 8; k++) {
            float4 wv = sW[k * 128 + c];
            wlo[k] = pk2(wv.x, wv.y);
            whi[k] = pk2(wv.z, wv.w);
        }
        #pragma unroll
        for (int r = 0; r < 2; r++) {
            float4 xv = x4[(size_t)(row0 + r) * 128 + c];
            unsigned long long xlo = pk2(xv.x, xv.y);
            unsigned long long xhi = pk2(xv.z, xv.w);
            #pragma unroll
            for (int k = 0; k < 8; k++) {
                fma2(acc2[r][k], xlo, wlo[k]);
                fma2(acc2[r][k], xhi, whi[k]);
            }
        }
    }

    // collapse packed halves, butterfly reduce across the warp
    float acc[2][8];
    #pragma unroll
    for (int r = 0; r < 2; r++)
        #pragma unroll
        for (int k = 0; k < 8; k++) {
            float s = upk_sum(acc2[r][k]);
            #pragma unroll
            for (int off = 16; off > 0; off >>= 1)
                s += __shfl_xor_sync(0xFFFFFFFFu, s, off);
            acc[r][k] = s;
        }

    if (lane < 2) {
        int row = row0 + lane;
        float4 mv;
        mv.x = gelu_exact(acc[lane][0]);
        mv.y = gelu_exact(acc[lane][1]);
        mv.z = gelu_exact(acc[lane][2]);
        mv.w = gelu_exact(acc[lane][3]);
        g_m[row] = mv;
        float4 uv;
        uv.x = acc[lane][4] + sB[0];
        uv.y = acc[lane][5] + sB[1];
        uv.z = acc[lane][6] + sB[2];
        uv.w = acc[lane][7] + sB[3];
        g_u[row] = uv;
    }
}

// ---------------- kernel 2: pair scatter #1 (node msgs -> edge sums) ----------------
// 4 pairs per thread (int4 index loads). Edge accumulators 8-way replicated,
// node counts 4-way replicated. Replica picked from thread id low bits.
__global__ __launch_bounds__(256) void k_scatter_edges(
    const int4* __restrict__ pn4,
    const int4* __restrict__ pe4)
{
    int t = blockIdx.x * blockDim.x + threadIdx.x;
    if (t >= NP / 4) return;
    int4 n4 = __ldg(&pn4[t]);
    int4 e4 = __ldg(&pe4[t]);
    int erep = (threadIdx.x & (NREP - 1)) * NE;
    int nrep = ((threadIdx.x >> 3) & (NSREP - 1)) * NN;

    #pragma unroll
    for (int j = 0; j < 4; j++) {
        int n = (j == 0) ? n4.x : (j == 1) ? n4.y : (j == 2) ? n4.z : n4.w;
        int e = (j == 0) ? e4.x : (j == 1) ? e4.y : (j == 2) ? e4.z : e4.w;
        float4 mv = g_m[n];
        atomicAdd(&g_s.esum[erep + e], mv);      // RED.128
        atomicAdd(&g_s.ecnt[erep + e], 1.0f);
        atomicAdd(&g_s.ncnt[nrep + n], 1.0f);
    }
}

// ---------------- kernel 3: edge mean (sum replicas) ----------------
__global__ void k_edge_mean() {
    int e = blockIdx.x * blockDim.x + threadIdx.x;
    if (e >= NE) return;
    float4 s = make_float4(0.f, 0.f, 0.f, 0.f);
    float cnt = 0.0f;
    #pragma unroll
    for (int r = 0; r < NREP; r++) {
        float4 v = g_s.esum[r * NE + e];
        s.x += v.x; s.y += v.y; s.z += v.z; s.w += v.w;
        cnt += g_s.ecnt[r * NE + e];
    }
    float inv = 1.0f / fmaxf(cnt, 1.0f);
    g_ef[e] = make_float4(s.x * inv, s.y * inv, s.z * inv, s.w * inv);
}

// ---------------- kernel 4: pair scatter #2 (edge means -> node sums) ----------------
__global__ __launch_bounds__(256) void k_scatter_nodes(
    const int4* __restrict__ pn4,
    const int4* __restrict__ pe4)
{
    int t = blockIdx.x * blockDim.x + threadIdx.x;
    if (t >= NP / 4) return;
    int4 n4 = __ldg(&pn4[t]);
    int4 e4 = __ldg(&pe4[t]);
    int nrep = (threadIdx.x & (NSREP - 1)) * NN;

    #pragma unroll
    for (int j = 0; j < 4; j++) {
        int n = (j == 0) ? n4.x : (j == 1) ? n4.y : (j == 2) ? n4.z : n4.w;
        int e = (j == 0) ? e4.x : (j == 1) ? e4.y : (j == 2) ? e4.z : e4.w;
        float4 ev = g_ef[e];
        atomicAdd(&g_s.nsum[nrep + n], ev);      // RED.128 (only atomic here)
    }
}

// ---------------- kernel 5: update + log_softmax (sum node replicas) ----------------
__global__ void k_final(float4* __restrict__ out4) {
    int i = blockIdx.x * blockDim.x + threadIdx.x;
    if (i >= NN) return;
    float4 u = g_u[i];
    float4 s = make_float4(0.f, 0.f, 0.f, 0.f);
    float cnt = 0.0f;
    #pragma unroll
    for (int r = 0; r < NSREP; r++) {
        float4 v = g_s.nsum[r * NN + i];
        s.x += v.x; s.y += v.y; s.z += v.z; s.w += v.w;
        cnt += g_s.ncnt[r * NN + i];
    }
    float inv = 1.0f / fmaxf(cnt, 1.0f);
    float h0 = gelu_exact(u.x + s.x * inv);
    float h1 = gelu_exact(u.y + s.y * inv);
    float h2 = gelu_exact(u.z + s.z * inv);
    float h3 = gelu_exact(u.w + s.w * inv);
    float mx = fmaxf(fmaxf(h0, h1), fmaxf(h2, h3));
    float lse = mx + logf(expf(h0 - mx) + expf(h1 - mx)
                        + expf(h2 - mx) + expf(h3 - mx));
    out4[i] = make_float4(h0 - lse, h1 - lse, h2 - lse, h3 - lse);
}

// ---------------- launch ----------------
extern "C" void kernel_launch(void* const* d_in, const int* in_sizes, int n_in,
                              void* d_out, int out_size) {
    const float* x         = (const float*)d_in[0];
    const int*   pair_node = (const int*)d_in[1];
    const int*   pair_edge = (const int*)d_in[2];
    const float* W_msg     = (const float*)d_in[3];
    const float* W_upd     = (const float*)d_in[4];
    const float* b_upd     = (const float*)d_in[5];
    float4* out4 = (float4*)d_out;

    // one memset node clears all accumulators (replaces k_init)
    void* scratch_ptr = nullptr;
    cudaGetSymbolAddress(&scratch_ptr, g_s);
    cudaMemsetAsync(scratch_ptr, 0, sizeof(Scratch));

    k_linear<<<NN / 16, 256>>>((const float4*)x,
                               (const float4*)W_msg,
                               (const float4*)W_upd,
                               b_upd);

    k_scatter_edges<<<(NP / 4 + 255) / 256, 256>>>((const int4*)pair_node,
                                                   (const int4*)pair_edge);

    k_edge_mean<<<(NE + 255) / 256, 256>>>();

    k_scatter_nodes<<<(NP / 4 + 255) / 256, 256>>>((const int4*)pair_node,
                                                   (const int4*)pair_edge);

    k_final<<<(NN + 255) / 256, 256>>>(out4);
}

// round 5
// speedup vs baseline: 1.0836x; 1.0836x over previous
#include <cuda_runtime.h>
#include <cuda_bf16.h>
#include <math.h>

#define NN 100000
#define NE 20000
#define NP 3200000
#define D  512
#define NREP  8                   // edge accumulator replicas
#define NSREP 4                   // node accumulator replicas

// ---------------- scratch (device globals; no allocation) ----------------
__device__ float4 g_m[NN];            // gelu(x @ Wmsg^T)         [N,4]
__device__ float4 g_u[NN];            // x @ Wupd^T + b           [N,4]
__device__ float4 g_ef[NE];           // edge means

// zero-initialized accumulators, packed so ONE memset clears them all
struct Scratch {
    float4 esum[NREP * NE];           // 2.56 MB
    float  ecnt[NREP * NE];           // 0.64 MB
    float4 nsum[NSREP * NN];          // 6.4 MB
    float  ncnt[NSREP * NN];          // 1.6 MB
};
__device__ Scratch g_s;

__device__ __forceinline__ float gelu_exact(float v) {
    return 0.5f * v * (1.0f + erff(v * 0.70710678118654752f));
}

// ---------------- packed f32x2 helpers (sm_100a) ----------------
__device__ __forceinline__ unsigned long long pk2(float a, float b) {
    unsigned long long r;
    asm("mov.b64 %0, {%1, %2};" : "=l"(r) : "f"(a), "f"(b));
    return r;
}
__device__ __forceinline__ void fma2(unsigned long long& d,
                                     unsigned long long a,
                                     unsigned long long b) {
    asm("fma.rn.f32x2 %0, %1, %2, %0;" : "+l"(d) : "l"(a), "l"(b));
}
__device__ __forceinline__ float upk_sum(unsigned long long v) {
    float x, y;
    asm("mov.b64 {%0, %1}, %2;" : "=f"(x), "=f"(y) : "l"(v));
    return x + y;
}

// ---------------- kernel 1: fused dual GEMV + GELU + pair counting ----------------
// Phase A: each warp computes 2 rows x 8 features (W in smem, x coalesced).
// Phase B (no sync needed): threads with tid < NP/4 also count pair
// multiplicities (ecnt, ncnt) — these REDs depend only on the index arrays,
// and overlap with the DRAM-bound GEMV of other warps/waves, keeping the
// LTS atomic ALUs busy while HBM is the binding resource.
__global__ __launch_bounds__(256) void k_linear(
    const float4* __restrict__ x4,      // [N, 128] float4
    const float4* __restrict__ wmsg4,   // [4, 128]
    const float4* __restrict__ wupd4,   // [4, 128]
    const float*  __restrict__ b_upd,   // [4]
    const int4*   __restrict__ pn4,
    const int4*   __restrict__ pe4)
{
    __shared__ float4 sW[8 * 128];
    __shared__ float  sB[4];

    int t = threadIdx.x;
    for (int i = t; i < 4 * 128; i += 256) sW[i] = wmsg4[i];
    for (int i = t; i < 4 * 128; i += 256) sW[4 * 128 + i] = wupd4[i];
    if (t < 4) sB[t] = b_upd[t];
    __syncthreads();

    int warp = t >> 5;
    int lane = t & 31;
    int row0 = (blockIdx.x * 8 + warp) * 2;   // N = 100000 = 6250 blocks * 16 rows

    unsigned long long acc2[2][8];
    #pragma unroll
    for (int r = 0; r < 2; r++)
        #pragma unroll
        for (int k = 0; k < 8; k++) acc2[r][k] = 0ull;

    #pragma unroll
    for (int i = 0; i < 4; i++) {
        int c = i * 32 + lane;                // float4 column index 0..127
        unsigned long long wlo[8], whi[8];
        #pragma unroll
        for (int k = 0; k < 8; k++) {
            float4 wv = sW[k * 128 + c];
            wlo[k] = pk2(wv.x, wv.y);
            whi[k] = pk2(wv.z, wv.w);
        }
        #pragma unroll
        for (int r = 0; r < 2; r++) {
            float4 xv = x4[(size_t)(row0 + r) * 128 + c];
            unsigned long long xlo = pk2(xv.x, xv.y);
            unsigned long long xhi = pk2(xv.z, xv.w);
            #pragma unroll
            for (int k = 0; k < 8; k++) {
                fma2(acc2[r][k], xlo, wlo[k]);
                fma2(acc2[r][k], xhi, whi[k]);
            }
        }
    }

    // collapse packed halves, butterfly reduce across the warp
    float acc[2][8];
    #pragma unroll
    for (int r = 0; r < 2; r++)
        #pragma unroll
        for (int k = 0; k < 8; k++) {
            float s = upk_sum(acc2[r][k]);
            #pragma unroll
            for (int off = 16; off > 0; off >>= 1)
                s += __shfl_xor_sync(0xFFFFFFFFu, s, off);
            acc[r][k] = s;
        }

    if (lane < 2) {
        int row = row0 + lane;
        float4 mv;
        mv.x = gelu_exact(acc[lane][0]);
        mv.y = gelu_exact(acc[lane][1]);
        mv.z = gelu_exact(acc[lane][2]);
        mv.w = gelu_exact(acc[lane][3]);
        g_m[row] = mv;
        float4 uv;
        uv.x = acc[lane][4] + sB[0];
        uv.y = acc[lane][5] + sB[1];
        uv.z = acc[lane][6] + sB[2];
        uv.w = acc[lane][7] + sB[3];
        g_u[row] = uv;
    }

    // ---- Phase B: pair multiplicity counting (index-only, overlaps GEMV) ----
    int tid = blockIdx.x * 256 + t;           // 1.6M threads, 800k chunks
    if (tid < NP / 4) {
        int4 n4 = __ldg(&pn4[tid]);
        int4 e4 = __ldg(&pe4[tid]);
        int erep = (t & (NREP - 1)) * NE;
        int nrep = ((t >> 3) & (NSREP - 1)) * NN;
        #pragma unroll
        for (int j = 0; j < 4; j++) {
            int n = (j == 0) ? n4.x : (j == 1) ? n4.y : (j == 2) ? n4.z : n4.w;
            int e = (j == 0) ? e4.x : (j == 1) ? e4.y : (j == 2) ? e4.z : e4.w;
            atomicAdd(&g_s.ecnt[erep + e], 1.0f);
            atomicAdd(&g_s.ncnt[nrep + n], 1.0f);
        }
    }
}

// ---------------- kernel 2: pair scatter #1 (node msgs -> edge sums) ----------------
// Now a single RED.128 per pair (counts moved into k_linear).
__global__ __launch_bounds__(256) void k_scatter_edges(
    const int4* __restrict__ pn4,
    const int4* __restrict__ pe4)
{
    int t = blockIdx.x * blockDim.x + threadIdx.x;
    if (t >= NP / 4) return;
    int4 n4 = __ldg(&pn4[t]);
    int4 e4 = __ldg(&pe4[t]);
    int erep = (threadIdx.x & (NREP - 1)) * NE;

    #pragma unroll
    for (int j = 0; j < 4; j++) {
        int n = (j == 0) ? n4.x : (j == 1) ? n4.y : (j == 2) ? n4.z : n4.w;
        int e = (j == 0) ? e4.x : (j == 1) ? e4.y : (j == 2) ? e4.z : e4.w;
        float4 mv = g_m[n];
        atomicAdd(&g_s.esum[erep + e], mv);      // RED.128 (only atomic here)
    }
}

// ---------------- kernel 3: edge mean (sum replicas) ----------------
__global__ void k_edge_mean() {
    int e = blockIdx.x * blockDim.x + threadIdx.x;
    if (e >= NE) return;
    float4 s = make_float4(0.f, 0.f, 0.f, 0.f);
    float cnt = 0.0f;
    #pragma unroll
    for (int r = 0; r < NREP; r++) {
        float4 v = g_s.esum[r * NE + e];
        s.x += v.x; s.y += v.y; s.z += v.z; s.w += v.w;
        cnt += g_s.ecnt[r * NE + e];
    }
    float inv = 1.0f / fmaxf(cnt, 1.0f);
    g_ef[e] = make_float4(s.x * inv, s.y * inv, s.z * inv, s.w * inv);
}

// ---------------- kernel 4: pair scatter #2 (edge means -> node sums) ----------------
__global__ __launch_bounds__(256) void k_scatter_nodes(
    const int4* __restrict__ pn4,
    const int4* __restrict__ pe4)
{
    int t = blockIdx.x * blockDim.x + threadIdx.x;
    if (t >= NP / 4) return;
    int4 n4 = __ldg(&pn4[t]);
    int4 e4 = __ldg(&pe4[t]);
    int nrep = (threadIdx.x & (NSREP - 1)) * NN;

    #pragma unroll
    for (int j = 0; j < 4; j++) {
        int n = (j == 0) ? n4.x : (j == 1) ? n4.y : (j == 2) ? n4.z : n4.w;
        int e = (j == 0) ? e4.x : (j == 1) ? e4.y : (j == 2) ? e4.z : e4.w;
        float4 ev = g_ef[e];
        atomicAdd(&g_s.nsum[nrep + n], ev);      // RED.128 (only atomic here)
    }
}

// ---------------- kernel 5: update + log_softmax (sum node replicas) ----------------
__global__ void k_final(float4* __restrict__ out4) {
    int i = blockIdx.x * blockDim.x + threadIdx.x;
    if (i >= NN) return;
    float4 u = g_u[i];
    float4 s = make_float4(0.f, 0.f, 0.f, 0.f);
    float cnt = 0.0f;
    #pragma unroll
    for (int r = 0; r < NSREP; r++) {
        float4 v = g_s.nsum[r * NN + i];
        s.x += v.x; s.y += v.y; s.z += v.z; s.w += v.w;
        cnt += g_s.ncnt[r * NN + i];
    }
    float inv = 1.0f / fmaxf(cnt, 1.0f);
    float h0 = gelu_exact(u.x + s.x * inv);
    float h1 = gelu_exact(u.y + s.y * inv);
    float h2 = gelu_exact(u.z + s.z * inv);
    float h3 = gelu_exact(u.w + s.w * inv);
    float mx = fmaxf(fmaxf(h0, h1), fmaxf(h2, h3));
    float lse = mx + logf(expf(h0 - mx) + expf(h1 - mx)
                        + expf(h2 - mx) + expf(h3 - mx));
    out4[i] = make_float4(h0 - lse, h1 - lse, h2 - lse, h3 - lse);
}

// ---------------- launch ----------------
extern "C" void kernel_launch(void* const* d_in, const int* in_sizes, int n_in,
                              void* d_out, int out_size) {
    const float* x         = (const float*)d_in[0];
    const int*   pair_node = (const int*)d_in[1];
    const int*   pair_edge = (const int*)d_in[2];
    const float* W_msg     = (const float*)d_in[3];
    const float* W_upd     = (const float*)d_in[4];
    const float* b_upd     = (const float*)d_in[5];
    float4* out4 = (float4*)d_out;

    // one memset node clears all accumulators
    void* scratch_ptr = nullptr;
    cudaGetSymbolAddress(&scratch_ptr, g_s);
    cudaMemsetAsync(scratch_ptr, 0, sizeof(Scratch));

    k_linear<<<NN / 16, 256>>>((const float4*)x,
                               (const float4*)W_msg,
                               (const float4*)W_upd,
                               b_upd,
                               (const int4*)pair_node,
                               (const int4*)pair_edge);

    k_scatter_edges<<<(NP / 4 + 255) / 256, 256>>>((const int4*)pair_node,
                                                   (const int4*)pair_edge);

    k_edge_mean<<<(NE + 255) / 256, 256>>>();

    k_scatter_nodes<<<(NP / 4 + 255) / 256, 256>>>((const int4*)pair_node,
                                                   (const int4*)pair_edge);

    k_final<<<(NN + 255) / 256, 256>>>(out4);
}